// round 1
// baseline (speedup 1.0000x reference)
#include <cuda_runtime.h>
#include <math.h>

// Problem constants
#define NBc   16
#define NAc   5
#define NKc   9
#define NCc   13
#define NHc   38
#define NWc   38
#define MAXTc 50
#define NPIX  (NHc*NWc)        // 1444
#define NANCH (NAc*NPIX)       // 7220
#define NTOTc (NBc*NANCH)      // 115520
#define CHPA  (2*NKc+1+NCc)    // 32 channels per anchor

#define TPB   256
#define BPB   ((NANCH + TPB - 1)/TPB)  // 29 blocks per batch
#define NBLK  (NBc*BPB)                // 464 blocks total

// corner-conf constants: SHARP=2, TH=80
// c = (exp(2*(1 - d/80)) - 1)/(e^2 - 1), mean over 9 corners
// We accumulate s = sum_k (exp(...)-1); conf = s / (9*(e^2-1)) = s / 57.5015049
#define DENOM9   57.50150489f
#define STHRESH  34.50090293f   // 0.6 * 9 * (e^2 - 1)

// -------- per-target metadata scratch (device globals; no allocation) --------
__device__ int   g_valid[NBc*MAXTc];
__device__ int   g_best [NBc*MAXTc];
__device__ int   g_gi   [NBc*MAXTc];
__device__ int   g_gj   [NBc*MAXTc];
__device__ float g_tconf[NBc*MAXTc];
__device__ float g_cls  [NBc*MAXTc];
__device__ float g_gx   [NBc*MAXTc*NKc];  // corner x in pixels (gt_x * 640)
__device__ float g_gy   [NBc*MAXTc*NKc];  // corner y in pixels (gt_y * 480)
__device__ float g_vx   [NBc*MAXTc*NKc];  // coord target: gt_x*nW - gi0
__device__ float g_vy   [NBc*MAXTc*NKc];  // coord target: gt_y*nH - gj0
__device__ float g_part_base[NBLK];
__device__ float g_part_conf[NBLK];

__device__ __forceinline__ float sigf(float x) { return 1.0f / (1.0f + expf(-x)); }

// ============================================================================
// Kernel 1: per (b,t) target metadata.  800 threads total.
// ============================================================================
__global__ void k_meta(const float* __restrict__ out,
                       const float* __restrict__ tgt,
                       const float* __restrict__ anc) {
    int id = blockIdx.x * blockDim.x + threadIdx.x;
    if (id >= NBc * MAXTc) return;
    int b = id / MAXTc, t = id % MAXTc;
    const float* tb = tgt + (size_t)(b * MAXTc + t) * 21;

    // valid = cumprod(gt_x[:, :, 0] != 0): prefix validity
    int valid = 1;
    for (int tt = 0; tt <= t; ++tt) {
        if (tgt[(size_t)(b * MAXTc + tt) * 21 + 1] == 0.0f) { valid = 0; break; }
    }
    g_valid[id] = valid;
    if (!valid) return;

    // best anchor by IoU (first-max, matching jnp.argmax)
    float gw = tb[19] * (float)NWc;
    float gh = tb[20] * (float)NHc;
    float best = -1.0f; int bn = 0;
    for (int a = 0; a < NAc; ++a) {
        float aw = anc[2*a], ah = anc[2*a+1];
        float cw = fminf(gw, aw), ch = fminf(gh, ah);
        float iou = 0.0f;
        if (cw > 0.0f && ch > 0.0f) {
            float ca = cw * ch;
            iou = ca / (gw * gh + aw * ah - ca);
        }
        if (iou > best) { best = iou; bn = a; }
    }
    int gi0 = (int)floorf(tb[1] * (float)NWc);
    int gj0 = (int)floorf(tb[2] * (float)NHc);
    g_best[id] = bn; g_gi[id] = gi0; g_gj[id] = gj0;
    g_cls[id] = tb[0];

    #pragma unroll
    for (int k = 0; k < NKc; ++k) {
        float gx = tb[1 + 2*k], gy = tb[2 + 2*k];
        g_gx[id*NKc + k] = gx * 640.0f;
        g_gy[id*NKc + k] = gy * 480.0f;
        g_vx[id*NKc + k] = gx * (float)NWc - (float)gi0;
        g_vy[id*NKc + k] = gy * (float)NHc - (float)gj0;
    }

    // tconf: corner conf vs predictions at the pidx-shifted cell
    long long p = (long long)b * NANCH - NPIX + (long long)gj0 * NWc + gi0;
    long long tot = NTOTc;
    p = ((p % tot) + tot) % tot;
    int b2  = (int)(p / NANCH);
    int rem = (int)(p % NANCH);
    int a2  = rem / NPIX;
    int pix = rem % NPIX;
    int h2 = pix / NWc, w2 = pix % NWc;
    const float* baseo = out + ((size_t)(b2 * NAc + a2) * CHPA) * NPIX + pix;

    float s = 0.0f;
    #pragma unroll
    for (int k = 0; k < NKc; ++k) {
        float xv = baseo[(2*k)   * NPIX];
        float yv = baseo[(2*k+1) * NPIX];
        if (k == 0) { xv = sigf(xv); yv = sigf(yv); }
        float Px = (xv + (float)w2) * (640.0f / (float)NWc);
        float Py = (yv + (float)h2) * (480.0f / (float)NHc);
        float dx = g_gx[id*NKc + k] - Px;
        float dy = g_gy[id*NKc + k] - Py;
        float d2 = fmaf(dx, dx, dy * dy);
        if (d2 < 6400.0f) s += expf(2.0f - sqrtf(d2) * 0.025f) - 1.0f;
    }
    g_tconf[id] = s * (1.0f / DENOM9);
}

// ============================================================================
// Kernel 2: per-cell losses.  One thread per (a,h,w) cell; blocks grouped by b.
// ============================================================================
__global__ void __launch_bounds__(TPB)
k_main(const float* __restrict__ out) {
    __shared__ int   s_nv;
    __shared__ int   s_best[MAXTc], s_gi[MAXTc], s_gj[MAXTc];
    __shared__ float s_tconf[MAXTc], s_cls[MAXTc];
    __shared__ float s_gx[MAXTc*NKc], s_gy[MAXTc*NKc];
    __shared__ float s_vx[MAXTc*NKc], s_vy[MAXTc*NKc];
    __shared__ float red[TPB];

    int b = blockIdx.x / BPB;
    if (threadIdx.x == 0) {
        int nv = 0;
        while (nv < MAXTc && g_valid[b*MAXTc + nv]) nv++;
        s_nv = nv;
    }
    for (int i = threadIdx.x; i < MAXTc; i += TPB) {
        int id = b*MAXTc + i;
        s_best[i] = g_best[id]; s_gi[i] = g_gi[id]; s_gj[i] = g_gj[id];
        s_tconf[i] = g_tconf[id]; s_cls[i] = g_cls[id];
    }
    for (int i = threadIdx.x; i < MAXTc*NKc; i += TPB) {
        int id = b*MAXTc*NKc + i;
        s_gx[i] = g_gx[id]; s_gy[i] = g_gy[id];
        s_vx[i] = g_vx[id]; s_vy[i] = g_vy[id];
    }
    __syncthreads();

    int cell = (blockIdx.x % BPB) * TPB + threadIdx.x;
    float baseLoss = 0.0f, confLoss = 0.0f;

    if (cell < NANCH) {
        int a   = cell / NPIX;
        int pix = cell % NPIX;
        int h = pix / NWc, w = pix % NWc;
        const float* baseo = out + ((size_t)(b * NAc + a) * CHPA) * NPIX + pix;

        float xr[NKc], yr[NKc], Px[NKc], Py[NKc];
        #pragma unroll
        for (int k = 0; k < NKc; ++k) {
            float xv = baseo[(2*k)   * NPIX];
            float yv = baseo[(2*k+1) * NPIX];
            if (k == 0) { xv = sigf(xv); yv = sigf(yv); }
            xr[k] = xv; yr[k] = yv;
            Px[k] = (xv + (float)w) * (640.0f / (float)NWc);
            Py[k] = (yv + (float)h) * (480.0f / (float)NHc);
        }
        float confv = sigf(baseo[(2*NKc) * NPIX]);

        int m = -1;          // matched target (last-write-wins like the scatter)
        float cur = 0.0f;    // scaled silence conf (max over targets of sum_k)
        int nv = s_nv;
        for (int t = 0; t < nv; ++t) {
            if (s_best[t] == a && s_gi[t] == w && s_gj[t] == h) m = t;
            float ssum = 0.0f;
            #pragma unroll
            for (int k = 0; k < NKc; ++k) {
                float dx = Px[k] - s_gx[t*NKc + k];
                float dy = Py[k] - s_gy[t*NKc + k];
                float d2 = fmaf(dx, dx, dy * dy);
                if (d2 < 6400.0f) ssum += expf(2.0f - sqrtf(d2) * 0.025f) - 1.0f;
            }
            cur = fmaxf(cur, ssum);
        }

        if (m >= 0) {
            // coord loss
            #pragma unroll
            for (int k = 0; k < NKc; ++k) {
                float dx = xr[k] - s_vx[m*NKc + k];
                float dy = yr[k] - s_vy[m*NKc + k];
                baseLoss += 0.5f * (dx*dx + dy*dy);
            }
            // class CE
            float l[NCc]; float mx = -1e30f;
            #pragma unroll
            for (int c = 0; c < NCc; ++c) {
                l[c] = baseo[(2*NKc + 1 + c) * NPIX];
                mx = fmaxf(mx, l[c]);
            }
            float se = 0.0f;
            #pragma unroll
            for (int c = 0; c < NCc; ++c) se += expf(l[c] - mx);
            int lab = (int)s_cls[m];
            lab = lab < 0 ? 0 : (lab > NCc - 1 ? NCc - 1 : lab);
            baseLoss += logf(se) + mx - l[lab];
            // object conf loss (scale 5): 0.5 * 5 * (conf - tconf)^2
            float dc = confv - s_tconf[m];
            confLoss = 2.5f * dc * dc;
        } else {
            // no-object conf loss unless silenced (cur_conf > 0.6)
            if (cur <= STHRESH) confLoss = 0.5f * confv * confv;
        }
    }

    // deterministic block reduction
    red[threadIdx.x] = baseLoss;
    __syncthreads();
    for (int s = TPB/2; s > 0; s >>= 1) {
        if (threadIdx.x < s) red[threadIdx.x] += red[threadIdx.x + s];
        __syncthreads();
    }
    if (threadIdx.x == 0) g_part_base[blockIdx.x] = red[0];
    __syncthreads();
    red[threadIdx.x] = confLoss;
    __syncthreads();
    for (int s = TPB/2; s > 0; s >>= 1) {
        if (threadIdx.x < s) red[threadIdx.x] += red[threadIdx.x + s];
        __syncthreads();
    }
    if (threadIdx.x == 0) g_part_conf[blockIdx.x] = red[0];
}

// ============================================================================
// Kernel 3: final deterministic reduction + epoch gating
// ============================================================================
__global__ void k_final(float* __restrict__ d_out, const void* __restrict__ epoch_ptr) {
    __shared__ float rb[512], rc[512];
    int i = threadIdx.x;
    rb[i] = (i < NBLK) ? g_part_base[i] : 0.0f;
    rc[i] = (i < NBLK) ? g_part_conf[i] : 0.0f;
    __syncthreads();
    for (int s = 256; s > 0; s >>= 1) {
        if (i < s) { rb[i] += rb[i + s]; rc[i] += rc[i + s]; }
        __syncthreads();
    }
    if (i == 0) {
        int ev = ((const int*)epoch_ptr)[0];
        // robustness: if epoch arrived as a float32 bit pattern, decode it
        if (ev > 1000000 || ev < -1000000) ev = (int)__int_as_float(ev);
        float total = rb[0];
        if (ev > 15) total += rc[0];
        d_out[0] = total;
    }
}

extern "C" void kernel_launch(void* const* d_in, const int* in_sizes, int n_in,
                              void* d_out, int out_size) {
    const float* out_t = (const float*)d_in[0];
    const float* tgt   = (const float*)d_in[1];
    const float* anc   = (const float*)d_in[2];
    const void*  epoch = d_in[3];
    float* loss = (float*)d_out;

    k_meta<<<(NBc*MAXTc + 127)/128, 128>>>(out_t, tgt, anc);
    k_main<<<NBLK, TPB>>>(out_t);
    k_final<<<1, 512>>>(loss, epoch);
}

// round 2
// speedup vs baseline: 1.2162x; 1.2162x over previous
#include <cuda_runtime.h>
#include <math.h>

// Problem constants
#define NBc   16
#define NAc   5
#define NKc   9
#define NCc   13
#define NHc   38
#define NWc   38
#define MAXTc 50
#define NPIX  (NHc*NWc)        // 1444
#define NANCH (NAc*NPIX)       // 7220
#define NTOTc (NBc*NANCH)      // 115520
#define CHPA  (2*NKc+1+NCc)    // 32 channels per anchor
#define TROW  21               // floats per target row

#define TPB   256
#define BPB   ((NANCH + TPB - 1)/TPB)  // 29 blocks per batch
#define NBLK  (NBc*BPB)                // 464 blocks total

// corner-conf: c = (exp(2*(1 - d/80)) - 1)/(e^2 - 1), mean over 9 corners.
// We carry s = sum_k(exp(...)-1); conf = s / (9*(e^2-1)).
#define DENOM9   57.50150489f
#define STHRESH  34.50090293f   // 0.6 * 9 * (e^2 - 1)

__device__ float g_part[NBLK][2];   // (baseLoss, confLoss) partials
__device__ int   g_cnt = 0;         // completion counter (reset each launch)

__device__ __forceinline__ float sigf(float x) { return 1.0f / (1.0f + expf(-x)); }

// ============================================================================
// Single main kernel: per-block meta (redundant per batch) + per-cell losses
// + last-block deterministic final reduction.
// ============================================================================
__global__ void __launch_bounds__(TPB)
k_main(const float* __restrict__ out,
       const float* __restrict__ tgt,
       const float* __restrict__ anc,
       const void*  __restrict__ epoch_ptr,
       float* __restrict__ d_out) {
    __shared__ float s_t[MAXTc*TROW];          // raw target rows (coalesced load)
    __shared__ int   s_nv;
    __shared__ int   s_best[MAXTc], s_gi[MAXTc], s_gj[MAXTc];
    __shared__ float s_tconf[MAXTc], s_cls[MAXTc];
    __shared__ float s_gx[MAXTc*NKc], s_gy[MAXTc*NKc];   // corner px coords
    __shared__ float s_vx[MAXTc*NKc], s_vy[MAXTc*NKc];   // coord targets
    __shared__ float red[TPB][2];

    const int b = blockIdx.x / BPB;

    // ---- load this batch's targets, coalesced ----
    for (int i = threadIdx.x; i < MAXTc*TROW; i += TPB)
        s_t[i] = tgt[(size_t)b * (MAXTc*TROW) + i];
    __syncthreads();

    // ---- validity prefix scan (shared, trivial) ----
    if (threadIdx.x == 0) {
        int nv = 0;
        while (nv < MAXTc && s_t[nv*TROW + 1] != 0.0f) nv++;
        s_nv = nv;
    }
    __syncthreads();
    const int nv = s_nv;

    // ---- per-target meta: one thread per valid target ----
    if (threadIdx.x < nv) {
        const int t = threadIdx.x;
        const float* tb = &s_t[t*TROW];

        // best anchor by IoU (first-max)
        float gw = tb[19] * (float)NWc;
        float gh = tb[20] * (float)NHc;
        float best = -1.0f; int bn = 0;
        #pragma unroll
        for (int a = 0; a < NAc; ++a) {
            float aw = anc[2*a], ah = anc[2*a+1];
            float cw = fminf(gw, aw), ch = fminf(gh, ah);
            float iou = 0.0f;
            if (cw > 0.0f && ch > 0.0f) {
                float ca = cw * ch;
                iou = ca / (gw * gh + aw * ah - ca);
            }
            if (iou > best) { best = iou; bn = a; }
        }
        int gi0 = (int)floorf(tb[1] * (float)NWc);
        int gj0 = (int)floorf(tb[2] * (float)NHc);
        s_best[t] = bn; s_gi[t] = gi0; s_gj[t] = gj0;
        s_cls[t] = tb[0];

        #pragma unroll
        for (int k = 0; k < NKc; ++k) {
            float gx = tb[1 + 2*k], gy = tb[2 + 2*k];
            s_gx[t*NKc + k] = gx * 640.0f;
            s_gy[t*NKc + k] = gy * 480.0f;
            s_vx[t*NKc + k] = gx * (float)NWc - (float)gi0;
            s_vy[t*NKc + k] = gy * (float)NHc - (float)gj0;
        }

        // tconf: corner conf vs predictions at the pidx-shifted cell
        long long p = (long long)b * NANCH - NPIX + (long long)gj0 * NWc + gi0;
        const long long tot = NTOTc;
        p = ((p % tot) + tot) % tot;
        int b2  = (int)(p / NANCH);
        int rem = (int)(p % NANCH);
        int a2  = rem / NPIX;
        int pix = rem % NPIX;
        int h2 = pix / NWc, w2 = pix % NWc;
        const float* baseo = out + ((size_t)(b2 * NAc + a2) * CHPA) * NPIX + pix;

        float s = 0.0f;
        #pragma unroll
        for (int k = 0; k < NKc; ++k) {
            float xv = baseo[(2*k)   * NPIX];
            float yv = baseo[(2*k+1) * NPIX];
            if (k == 0) { xv = sigf(xv); yv = sigf(yv); }
            float Px = (xv + (float)w2) * (640.0f / (float)NWc);
            float Py = (yv + (float)h2) * (480.0f / (float)NHc);
            float dx = s_gx[t*NKc + k] - Px;
            float dy = s_gy[t*NKc + k] - Py;
            float d2 = fmaf(dx, dx, dy * dy);
            if (d2 < 6400.0f) s += expf(2.0f - sqrtf(d2) * 0.025f) - 1.0f;
        }
        s_tconf[t] = s * (1.0f / DENOM9);
    }
    __syncthreads();

    // ---- per-cell loss ----
    const int cell = (blockIdx.x % BPB) * TPB + threadIdx.x;
    float baseLoss = 0.0f, confLoss = 0.0f;

    if (cell < NANCH) {
        int a   = cell / NPIX;
        int pix = cell % NPIX;
        int h = pix / NWc, w = pix % NWc;
        const float* baseo = out + ((size_t)(b * NAc + a) * CHPA) * NPIX + pix;

        float xr[NKc], yr[NKc], Px[NKc], Py[NKc];
        #pragma unroll
        for (int k = 0; k < NKc; ++k) {
            float xv = baseo[(2*k)   * NPIX];
            float yv = baseo[(2*k+1) * NPIX];
            if (k == 0) { xv = sigf(xv); yv = sigf(yv); }
            xr[k] = xv; yr[k] = yv;
            Px[k] = (xv + (float)w) * (640.0f / (float)NWc);
            Py[k] = (yv + (float)h) * (480.0f / (float)NHc);
        }
        float confv = sigf(baseo[(2*NKc) * NPIX]);

        int m = -1;          // matched target (last-write-wins like the scatter)
        float cur = 0.0f;    // silence conf (max over targets of corner sum)
        for (int t = 0; t < nv; ++t) {
            if (s_best[t] == a && s_gi[t] == w && s_gj[t] == h) m = t;
            float ssum = 0.0f;
            #pragma unroll
            for (int k = 0; k < NKc; ++k) {
                float dx = Px[k] - s_gx[t*NKc + k];
                float dy = Py[k] - s_gy[t*NKc + k];
                float d2 = fmaf(dx, dx, dy * dy);
                if (d2 < 6400.0f) ssum += expf(2.0f - sqrtf(d2) * 0.025f) - 1.0f;
            }
            cur = fmaxf(cur, ssum);
        }

        if (m >= 0) {
            // coord loss
            #pragma unroll
            for (int k = 0; k < NKc; ++k) {
                float dx = xr[k] - s_vx[m*NKc + k];
                float dy = yr[k] - s_vy[m*NKc + k];
                baseLoss += 0.5f * (dx*dx + dy*dy);
            }
            // class CE
            float l[NCc]; float mx = -1e30f;
            #pragma unroll
            for (int c = 0; c < NCc; ++c) {
                l[c] = baseo[(2*NKc + 1 + c) * NPIX];
                mx = fmaxf(mx, l[c]);
            }
            float se = 0.0f;
            #pragma unroll
            for (int c = 0; c < NCc; ++c) se += expf(l[c] - mx);
            int lab = (int)s_cls[m];
            lab = lab < 0 ? 0 : (lab > NCc - 1 ? NCc - 1 : lab);
            baseLoss += logf(se) + mx - l[lab];
            // object conf loss: 0.5 * OBJ_SCALE * (conf - tconf)^2
            float dc = confv - s_tconf[m];
            confLoss = 2.5f * dc * dc;
        } else {
            if (cur <= STHRESH) confLoss = 0.5f * confv * confv;  // no-obj
        }
    }

    // ---- deterministic block reduction (both terms in one pass) ----
    red[threadIdx.x][0] = baseLoss;
    red[threadIdx.x][1] = confLoss;
    __syncthreads();
    for (int s = TPB/2; s > 0; s >>= 1) {
        if (threadIdx.x < s) {
            red[threadIdx.x][0] += red[threadIdx.x + s][0];
            red[threadIdx.x][1] += red[threadIdx.x + s][1];
        }
        __syncthreads();
    }
    if (threadIdx.x == 0) {
        g_part[blockIdx.x][0] = red[0][0];
        g_part[blockIdx.x][1] = red[0][1];
    }

    // ---- last-block-done: deterministic final reduction ----
    __shared__ bool s_last;
    __threadfence();
    if (threadIdx.x == 0) {
        int old = atomicAdd(&g_cnt, 1);
        s_last = (old == NBLK - 1);
    }
    __syncthreads();
    if (!s_last) return;

    // fixed-order tree over fixed indices -> bit-deterministic
    float rb = 0.0f, rc = 0.0f;
    if (threadIdx.x < NBLK) { rb = g_part[threadIdx.x][0]; rc = g_part[threadIdx.x][1]; }
    int extra = threadIdx.x + TPB;
    if (extra < NBLK) { rb += g_part[extra][0]; rc += g_part[extra][1]; }
    red[threadIdx.x][0] = rb;
    red[threadIdx.x][1] = rc;
    __syncthreads();
    for (int s = TPB/2; s > 0; s >>= 1) {
        if (threadIdx.x < s) {
            red[threadIdx.x][0] += red[threadIdx.x + s][0];
            red[threadIdx.x][1] += red[threadIdx.x + s][1];
        }
        __syncthreads();
    }
    if (threadIdx.x == 0) {
        int ev = ((const int*)epoch_ptr)[0];
        if (ev > 1000000 || ev < -1000000) ev = (int)__int_as_float(ev);
        float total = red[0][0];
        if (ev > 15) total += red[0][1];
        d_out[0] = total;
        g_cnt = 0;   // reset for graph replay
    }
}

extern "C" void kernel_launch(void* const* d_in, const int* in_sizes, int n_in,
                              void* d_out, int out_size) {
    const float* out_t = (const float*)d_in[0];
    const float* tgt   = (const float*)d_in[1];
    const float* anc   = (const float*)d_in[2];
    const void*  epoch = d_in[3];
    k_main<<<NBLK, TPB>>>(out_t, tgt, anc, epoch, (float*)d_out);
}